// round 1
// baseline (speedup 1.0000x reference)
#include <cuda_runtime.h>
#include <math.h>

#define E_DIM   1024
#define HID_DIM 4096
#define M_TOT   16384          // B*S = 4*4096
#define WSZ     64
#define NWIN    256            // 4 * 64 windows of 64 tokens
#define SM_SCALE 0.03125f      // 1024^-0.5
#define LN_EPS  1e-5f

// -------- scratch (device globals; no allocation allowed) --------
__device__ float g_q  [M_TOT * E_DIM];
__device__ float g_k  [M_TOT * E_DIM];
__device__ float g_v  [M_TOT * E_DIM];
__device__ float g_att[M_TOT * E_DIM];
__device__ float g_x1 [M_TOT * E_DIM];
__device__ float g_h  [M_TOT * HID_DIM];
__device__ float g_f  [M_TOT * E_DIM];

// ====================================================================
// SGEMM: C[M,N] = A[M,K] @ B[K,N] + bias (+ReLU). Row-major everything.
// 128x128 block tile, BK=16, 256 threads, 8x8 per-thread microtile.
// Requires M%128==0, N%128==0, K%16==0 (true for all shapes here).
// ====================================================================
template <bool RELU>
__global__ __launch_bounds__(256) void sgemm_kernel(
    const float* __restrict__ A, const float* __restrict__ B,
    const float* __restrict__ bias, float* __restrict__ C,
    int M, int N, int K)
{
    __shared__ float sA[16][132];   // transposed A tile, padded
    __shared__ float sB[16][128];

    const int tid = threadIdx.x;
    const int bm0 = blockIdx.y * 128;
    const int bn0 = blockIdx.x * 128;
    const int tm0 = (tid / 16) * 8;
    const int tn0 = (tid % 16) * 8;

    // load indices
    const int ar = tid >> 2;          // 0..63
    const int ac = (tid & 3) * 4;     // 0,4,8,12
    const int br = tid >> 5;          // 0..7
    const int bc = (tid & 31) * 4;    // 0..124

    float acc[8][8];
#pragma unroll
    for (int i = 0; i < 8; i++)
#pragma unroll
        for (int j = 0; j < 8; j++) acc[i][j] = 0.f;

    for (int k0 = 0; k0 < K; k0 += 16) {
#pragma unroll
        for (int t = 0; t < 2; t++) {
            int row = ar + t * 64;
            float4 av = *(const float4*)(A + (size_t)(bm0 + row) * K + k0 + ac);
            sA[ac + 0][row] = av.x;
            sA[ac + 1][row] = av.y;
            sA[ac + 2][row] = av.z;
            sA[ac + 3][row] = av.w;
        }
#pragma unroll
        for (int t = 0; t < 2; t++) {
            int row = br + t * 8;
            *(float4*)(&sB[row][bc]) =
                *(const float4*)(B + (size_t)(k0 + row) * N + bn0 + bc);
        }
        __syncthreads();

#pragma unroll
        for (int kk = 0; kk < 16; kk++) {
            float af[8], bf[8];
            *(float4*)(af)     = *(const float4*)(&sA[kk][tm0]);
            *(float4*)(af + 4) = *(const float4*)(&sA[kk][tm0 + 4]);
            *(float4*)(bf)     = *(const float4*)(&sB[kk][tn0]);
            *(float4*)(bf + 4) = *(const float4*)(&sB[kk][tn0 + 4]);
#pragma unroll
            for (int i = 0; i < 8; i++)
#pragma unroll
                for (int j = 0; j < 8; j++)
                    acc[i][j] += af[i] * bf[j];
        }
        __syncthreads();
    }

    float bfrag[8];
#pragma unroll
    for (int j = 0; j < 8; j++) bfrag[j] = bias[bn0 + tn0 + j];

#pragma unroll
    for (int i = 0; i < 8; i++) {
        size_t rowoff = (size_t)(bm0 + tm0 + i) * N + bn0 + tn0;
#pragma unroll
        for (int j = 0; j < 8; j += 4) {
            float4 o;
            o.x = acc[i][j + 0] + bfrag[j + 0];
            o.y = acc[i][j + 1] + bfrag[j + 1];
            o.z = acc[i][j + 2] + bfrag[j + 2];
            o.w = acc[i][j + 3] + bfrag[j + 3];
            if (RELU) {
                o.x = fmaxf(o.x, 0.f); o.y = fmaxf(o.y, 0.f);
                o.z = fmaxf(o.z, 0.f); o.w = fmaxf(o.w, 0.f);
            }
            *(float4*)(C + rowoff + j) = o;
        }
    }
}

// ====================================================================
// Window attention: one block per window (64 tokens, 1024-dim features)
// scores = Q K^T * scale -> softmax -> P @ V
// ====================================================================
__global__ __launch_bounds__(256) void attn_kernel(
    const float* __restrict__ Q, const float* __restrict__ K,
    const float* __restrict__ V, float* __restrict__ O)
{
    __shared__ float sQ [64 * 32];
    __shared__ float sKV[64 * 33];   // padded: conflict-free strided reads
    __shared__ float sS [64 * 64];

    const int tid  = threadIdx.x;
    const size_t base = (size_t)blockIdx.x * 64 * E_DIM;

    // ---- phase 1: scores[q][k] = sum_c Q[q][c]*K[k][c] ----
    const int kcol = tid & 63;            // 0..63
    const int q0   = (tid >> 6) * 16;     // 0,16,32,48
    float acc[16];
#pragma unroll
    for (int i = 0; i < 16; i++) acc[i] = 0.f;

    for (int c0 = 0; c0 < E_DIM; c0 += 32) {
        for (int idx = tid; idx < 64 * 32; idx += 256) {
            int r = idx >> 5, c = idx & 31;
            sQ [r * 32 + c] = Q[base + (size_t)r * E_DIM + c0 + c];
            sKV[r * 33 + c] = K[base + (size_t)r * E_DIM + c0 + c];
        }
        __syncthreads();
#pragma unroll
        for (int c = 0; c < 32; c++) {
            float kv = sKV[kcol * 33 + c];
#pragma unroll
            for (int i = 0; i < 16; i++)
                acc[i] += sQ[(q0 + i) * 32 + c] * kv;
        }
        __syncthreads();
    }
#pragma unroll
    for (int i = 0; i < 16; i++)
        sS[(q0 + i) * 64 + kcol] = acc[i] * SM_SCALE;
    __syncthreads();

    // ---- phase 2: softmax over k (rows of sS), warp per 8 rows ----
    const int lane = tid & 31, wrp = tid >> 5;
    for (int r = wrp * 8; r < wrp * 8 + 8; r++) {
        float v0 = sS[r * 64 + lane];
        float v1 = sS[r * 64 + 32 + lane];
        float m = fmaxf(v0, v1);
#pragma unroll
        for (int o = 16; o > 0; o >>= 1)
            m = fmaxf(m, __shfl_xor_sync(0xffffffffu, m, o));
        float e0 = __expf(v0 - m), e1 = __expf(v1 - m);
        float s = e0 + e1;
#pragma unroll
        for (int o = 16; o > 0; o >>= 1)
            s += __shfl_xor_sync(0xffffffffu, s, o);
        float inv = 1.0f / s;
        sS[r * 64 + lane]      = e0 * inv;
        sS[r * 64 + 32 + lane] = e1 * inv;
    }
    __syncthreads();

    // ---- phase 3: O = P @ V, 32-wide E chunks ----
    const int ecol = tid & 31;
    const int q0b  = (tid >> 5) * 8;      // 0..56
    for (int c0 = 0; c0 < E_DIM; c0 += 32) {
        for (int idx = tid; idx < 64 * 32; idx += 256) {
            int r = idx >> 5, c = idx & 31;
            sKV[r * 33 + c] = V[base + (size_t)r * E_DIM + c0 + c];
        }
        __syncthreads();
        float oacc[8];
#pragma unroll
        for (int i = 0; i < 8; i++) oacc[i] = 0.f;
#pragma unroll
        for (int k = 0; k < 64; k++) {
            float vv = sKV[k * 33 + ecol];
#pragma unroll
            for (int i = 0; i < 8; i++)
                oacc[i] += sS[(q0b + i) * 64 + k] * vv;
        }
#pragma unroll
        for (int i = 0; i < 8; i++)
            O[base + (size_t)(q0b + i) * E_DIM + c0 + ecol] = oacc[i];
        __syncthreads();
    }
}

// ====================================================================
// Y = LayerNorm(A + R) * gamma + beta     (one block per row, E=1024)
// ====================================================================
__global__ __launch_bounds__(256) void add_ln_kernel(
    const float* __restrict__ A, const float* __restrict__ R,
    const float* __restrict__ g, const float* __restrict__ b,
    float* __restrict__ Y)
{
    const size_t off = (size_t)blockIdx.x * E_DIM;
    const int tid = threadIdx.x;
    float v[4];
    float s = 0.f, s2 = 0.f;
#pragma unroll
    for (int i = 0; i < 4; i++) {
        int c = tid + i * 256;
        float t = A[off + c] + R[off + c];
        v[i] = t; s += t; s2 += t * t;
    }
#pragma unroll
    for (int o = 16; o > 0; o >>= 1) {
        s  += __shfl_xor_sync(0xffffffffu, s,  o);
        s2 += __shfl_xor_sync(0xffffffffu, s2, o);
    }
    __shared__ float rs[8], rs2[8];
    __shared__ float s_mean, s_rstd;
    const int lane = tid & 31, wrp = tid >> 5;
    if (lane == 0) { rs[wrp] = s; rs2[wrp] = s2; }
    __syncthreads();
    if (tid == 0) {
        float a = 0.f, a2 = 0.f;
#pragma unroll
        for (int i = 0; i < 8; i++) { a += rs[i]; a2 += rs2[i]; }
        float mean = a * (1.0f / E_DIM);
        float var  = a2 * (1.0f / E_DIM) - mean * mean;
        s_mean = mean;
        s_rstd = rsqrtf(var + LN_EPS);
    }
    __syncthreads();
    const float mean = s_mean, rstd = s_rstd;
#pragma unroll
    for (int i = 0; i < 4; i++) {
        int c = tid + i * 256;
        Y[off + c] = (v[i] - mean) * rstd * g[c] + b[c];
    }
}

// ====================================================================
extern "C" void kernel_launch(void* const* d_in, const int* in_sizes, int n_in,
                              void* d_out, int out_size)
{
    (void)in_sizes; (void)n_in; (void)out_size;
    const float* x   = (const float*)d_in[0];
    const float* Wq  = (const float*)d_in[1];
    const float* bq  = (const float*)d_in[2];
    const float* Wk  = (const float*)d_in[3];
    const float* bk  = (const float*)d_in[4];
    const float* Wv  = (const float*)d_in[5];
    const float* bv  = (const float*)d_in[6];
    const float* g1  = (const float*)d_in[7];
    const float* be1 = (const float*)d_in[8];
    const float* W1  = (const float*)d_in[9];
    const float* b1  = (const float*)d_in[10];
    const float* W2  = (const float*)d_in[11];
    const float* b2  = (const float*)d_in[12];
    const float* g2  = (const float*)d_in[13];
    const float* be2 = (const float*)d_in[14];
    float* out = (float*)d_out;

    float *q, *k, *v, *att, *x1, *h, *f;
    cudaGetSymbolAddress((void**)&q,   g_q);
    cudaGetSymbolAddress((void**)&k,   g_k);
    cudaGetSymbolAddress((void**)&v,   g_v);
    cudaGetSymbolAddress((void**)&att, g_att);
    cudaGetSymbolAddress((void**)&x1,  g_x1);
    cudaGetSymbolAddress((void**)&h,   g_h);
    cudaGetSymbolAddress((void**)&f,   g_f);

    dim3 blk(256);
    dim3 grid_qkv(E_DIM / 128, M_TOT / 128);     // (8, 128)
    dim3 grid_ffn1(HID_DIM / 128, M_TOT / 128);  // (32, 128)
    dim3 grid_ffn2(E_DIM / 128, M_TOT / 128);    // (8, 128)

    // QKV projections
    sgemm_kernel<false><<<grid_qkv, blk>>>(x, Wq, bq, q, M_TOT, E_DIM, E_DIM);
    sgemm_kernel<false><<<grid_qkv, blk>>>(x, Wk, bk, k, M_TOT, E_DIM, E_DIM);
    sgemm_kernel<false><<<grid_qkv, blk>>>(x, Wv, bv, v, M_TOT, E_DIM, E_DIM);

    // per-window attention
    attn_kernel<<<NWIN, blk>>>(q, k, v, att);

    // x1 = LN(x + att)
    add_ln_kernel<<<M_TOT, blk>>>(x, att, g1, be1, x1);

    // FFN
    sgemm_kernel<true ><<<grid_ffn1, blk>>>(x1, W1, b1, h, M_TOT, HID_DIM, E_DIM);
    sgemm_kernel<false><<<grid_ffn2, blk>>>(h,  W2, b2, f, M_TOT, E_DIM, HID_DIM);

    // out = LN(x1 + f)
    add_ln_kernel<<<M_TOT, blk>>>(x1, f, g2, be2, out);
}

// round 2
// speedup vs baseline: 2.3455x; 2.3455x over previous
#include <cuda_runtime.h>
#include <cuda_bf16.h>
#include <math.h>
#include <stdint.h>

#define E_DIM   1024
#define HID_DIM 4096
#define M_TOT   16384          // B*S = 4*4096
#define NWIN    256            // 4*64 windows of 64 tokens
#define SM_SCALE 0.03125f      // 1024^-0.5
#define LN_EPS  1e-5f

#define BM 128
#define BN 128
#define BKE 32                 // K elems per stage
#define SROW 40                // padded row length in bf16 elems (80B, 16B-mult)
#define SROW32 20              // in u32
#define PLANE_B 10240          // bytes per plane (128*40*2)
#define PLANE32 2560           // u32 per plane
#define STAGE_B 40960          // 4 planes
#define SMEM_TOTAL (2*STAGE_B) // 81920

// -------- scratch (device globals; no allocation allowed) --------
__device__ float g_q  [M_TOT * E_DIM];
__device__ float g_k  [M_TOT * E_DIM];
__device__ float g_v  [M_TOT * E_DIM];
__device__ float g_att[M_TOT * E_DIM];
__device__ float g_x1 [M_TOT * E_DIM];
__device__ float g_f  [M_TOT * E_DIM];

__device__ __nv_bfloat16 g_xh [M_TOT * E_DIM];
__device__ __nv_bfloat16 g_xl [M_TOT * E_DIM];
__device__ __nv_bfloat16 g_x1h[M_TOT * E_DIM];
__device__ __nv_bfloat16 g_x1l[M_TOT * E_DIM];
__device__ __nv_bfloat16 g_hh [M_TOT * HID_DIM];
__device__ __nv_bfloat16 g_hl [M_TOT * HID_DIM];

__device__ __nv_bfloat16 g_wqh[E_DIM * E_DIM];
__device__ __nv_bfloat16 g_wql[E_DIM * E_DIM];
__device__ __nv_bfloat16 g_wkh[E_DIM * E_DIM];
__device__ __nv_bfloat16 g_wkl[E_DIM * E_DIM];
__device__ __nv_bfloat16 g_wvh[E_DIM * E_DIM];
__device__ __nv_bfloat16 g_wvl[E_DIM * E_DIM];
__device__ __nv_bfloat16 g_w1h[E_DIM * HID_DIM];
__device__ __nv_bfloat16 g_w1l[E_DIM * HID_DIM];
__device__ __nv_bfloat16 g_w2h[HID_DIM * E_DIM];
__device__ __nv_bfloat16 g_w2l[HID_DIM * E_DIM];

// ====================================================================
// helpers
// ====================================================================
__device__ __forceinline__ void split_f32(float x, __nv_bfloat16& hi, __nv_bfloat16& lo) {
    hi = __float2bfloat16(x);
    lo = __float2bfloat16(x - __bfloat162float(hi));
}

__device__ __forceinline__ void mma16816(float* c, const uint32_t* a, const uint32_t* b) {
    asm volatile(
        "mma.sync.aligned.m16n8k16.row.col.f32.bf16.bf16.f32 "
        "{%0,%1,%2,%3},{%4,%5,%6,%7},{%8,%9},{%0,%1,%2,%3};"
        : "+f"(c[0]), "+f"(c[1]), "+f"(c[2]), "+f"(c[3])
        : "r"(a[0]), "r"(a[1]), "r"(a[2]), "r"(a[3]), "r"(b[0]), "r"(b[1]));
}

// ====================================================================
// elementwise split: X fp32 -> hi/lo bf16 planes
// ====================================================================
__global__ __launch_bounds__(256) void split_kernel(
    const float* __restrict__ X, __nv_bfloat16* __restrict__ H,
    __nv_bfloat16* __restrict__ L, int n4)
{
    int i = blockIdx.x * 256 + threadIdx.x;
    if (i >= n4) return;
    float4 v = ((const float4*)X)[i];
    __nv_bfloat16 h[4], l[4];
    split_f32(v.x, h[0], l[0]); split_f32(v.y, h[1], l[1]);
    split_f32(v.z, h[2], l[2]); split_f32(v.w, h[3], l[3]);
    __nv_bfloat162* Hp = (__nv_bfloat162*)(H + (size_t)i * 4);
    __nv_bfloat162* Lp = (__nv_bfloat162*)(L + (size_t)i * 4);
    Hp[0] = __nv_bfloat162{h[0], h[1]}; Hp[1] = __nv_bfloat162{h[2], h[3]};
    Lp[0] = __nv_bfloat162{l[0], l[1]}; Lp[1] = __nv_bfloat162{l[2], l[3]};
}

// ====================================================================
// weight transpose + split: W[K,N] fp32 -> Th[N,K], Tl[N,K] bf16
// ====================================================================
__global__ __launch_bounds__(256) void wtrans_kernel(
    const float* __restrict__ W, __nv_bfloat16* __restrict__ Th,
    __nv_bfloat16* __restrict__ Tl, int K, int N)
{
    __shared__ float t[32][33];
    const int tx = threadIdx.x, ty = threadIdx.y;
    const int n0 = blockIdx.x * 32, k0 = blockIdx.y * 32;
#pragma unroll
    for (int i = ty; i < 32; i += 8)
        t[i][tx] = W[(size_t)(k0 + i) * N + n0 + tx];
    __syncthreads();
#pragma unroll
    for (int i = ty; i < 32; i += 8) {
        float v = t[tx][i];
        __nv_bfloat16 hi, lo; split_f32(v, hi, lo);
        size_t o = (size_t)(n0 + i) * K + k0 + tx;
        Th[o] = hi; Tl[o] = lo;
    }
}

// ====================================================================
// GEMM (TN): C[M,N] = (Ah+Al)[M,K] @ (Bh+Bl)[N,K]^T + bias
//   3-term bf16 split via mma.sync m16n8k16.
//   EPI=0: C fp32.  EPI=1: relu, write hi/lo bf16 planes Ch/Cl.
// ====================================================================
template <int EPI>
__global__ __launch_bounds__(256) void gemm_tn(
    const __nv_bfloat16* __restrict__ Ah, const __nv_bfloat16* __restrict__ Al,
    const __nv_bfloat16* __restrict__ Bh, const __nv_bfloat16* __restrict__ Bl,
    const float* __restrict__ bias,
    float* __restrict__ C, __nv_bfloat16* __restrict__ Ch, __nv_bfloat16* __restrict__ Cl,
    int M, int N, int K)
{
    extern __shared__ __align__(16) char smem_raw[];
    const int tid = threadIdx.x;
    const int bm0 = blockIdx.y * BM;
    const int bn0 = blockIdx.x * BN;
    const int lane = tid & 31, w = tid >> 5;
    const int g = lane >> 2, q4 = lane & 3;
    const int wm = (w >> 2) * 64, wn = (w & 3) * 32;

    const uint32_t sbase = (uint32_t)__cvta_generic_to_shared(smem_raw);

    float acc[4][4][4];
#pragma unroll
    for (int i = 0; i < 4; i++)
#pragma unroll
        for (int j = 0; j < 4; j++)
#pragma unroll
            for (int r = 0; r < 4; r++) acc[i][j][r] = 0.f;

    const __nv_bfloat16* gp[4] = {Ah, Al, Bh, Bl};
    const int rb[4] = {bm0, bm0, bn0, bn0};

    auto load_stage = [&](int s, int k0) {
        uint32_t b = sbase + s * STAGE_B;
#pragma unroll
        for (int p = 0; p < 4; p++) {
#pragma unroll
            for (int h2 = 0; h2 < 2; h2++) {
                int c = tid + h2 * 256;
                int row = c >> 2, cc = c & 3;
                uint32_t sa = b + p * PLANE_B + (row * SROW + cc * 8) * 2;
                const void* gptr = gp[p] + (size_t)(rb[p] + row) * K + k0 + cc * 8;
                asm volatile("cp.async.cg.shared.global [%0],[%1],16;\n" ::"r"(sa), "l"(gptr));
            }
        }
        asm volatile("cp.async.commit_group;\n");
    };

    load_stage(0, 0);
    asm volatile("cp.async.wait_group 0;\n");
    __syncthreads();

    for (int k0 = 0; k0 < K; k0 += BKE) {
        int s = (k0 >> 5) & 1;
        if (k0 + BKE < K) load_stage(s ^ 1, k0 + BKE);

        const uint32_t* s32   = (const uint32_t*)(smem_raw) + s * (STAGE_B / 4);
        const uint32_t* sAh32 = s32;
        const uint32_t* sAl32 = s32 + PLANE32;
        const uint32_t* sBh32 = s32 + 2 * PLANE32;
        const uint32_t* sBl32 = s32 + 3 * PLANE32;

#pragma unroll
        for (int ks = 0; ks < 2; ks++) {
            const int cb = ks * 8 + q4;
            uint32_t ah[4][4], al[4][4], bh[4][2], bl[4][2];
#pragma unroll
            for (int tm = 0; tm < 4; tm++) {
                int r0 = wm + tm * 16 + g;
                ah[tm][0] = sAh32[r0 * SROW32 + cb];
                ah[tm][1] = sAh32[(r0 + 8) * SROW32 + cb];
                ah[tm][2] = sAh32[r0 * SROW32 + cb + 4];
                ah[tm][3] = sAh32[(r0 + 8) * SROW32 + cb + 4];
                al[tm][0] = sAl32[r0 * SROW32 + cb];
                al[tm][1] = sAl32[(r0 + 8) * SROW32 + cb];
                al[tm][2] = sAl32[r0 * SROW32 + cb + 4];
                al[tm][3] = sAl32[(r0 + 8) * SROW32 + cb + 4];
            }
#pragma unroll
            for (int tn = 0; tn < 4; tn++) {
                int r = wn + tn * 8 + g;
                bh[tn][0] = sBh32[r * SROW32 + cb];
                bh[tn][1] = sBh32[r * SROW32 + cb + 4];
                bl[tn][0] = sBl32[r * SROW32 + cb];
                bl[tn][1] = sBl32[r * SROW32 + cb + 4];
            }
#pragma unroll
            for (int tm = 0; tm < 4; tm++)
#pragma unroll
                for (int tn = 0; tn < 4; tn++) {
                    mma16816(acc[tm][tn], ah[tm], bh[tn]);
                    mma16816(acc[tm][tn], ah[tm], bl[tn]);
                    mma16816(acc[tm][tn], al[tm], bh[tn]);
                }
        }
        if (k0 + BKE < K) asm volatile("cp.async.wait_group 0;\n");
        __syncthreads();
    }

    // epilogue
#pragma unroll
    for (int tm = 0; tm < 4; tm++) {
#pragma unroll
        for (int tn = 0; tn < 4; tn++) {
            int r0 = bm0 + wm + tm * 16 + g;
            int col = bn0 + wn + tn * 8 + q4 * 2;
            float b0 = bias[col], b1 = bias[col + 1];
            float v00 = acc[tm][tn][0] + b0, v01 = acc[tm][tn][1] + b1;
            float v10 = acc[tm][tn][2] + b0, v11 = acc[tm][tn][3] + b1;
            if (EPI == 0) {
                *(float2*)(C + (size_t)r0 * N + col) = make_float2(v00, v01);
                *(float2*)(C + (size_t)(r0 + 8) * N + col) = make_float2(v10, v11);
            } else {
                v00 = fmaxf(v00, 0.f); v01 = fmaxf(v01, 0.f);
                v10 = fmaxf(v10, 0.f); v11 = fmaxf(v11, 0.f);
                __nv_bfloat16 h00, l00, h01, l01, h10, l10, h11, l11;
                split_f32(v00, h00, l00); split_f32(v01, h01, l01);
                split_f32(v10, h10, l10); split_f32(v11, h11, l11);
                *(__nv_bfloat162*)(Ch + (size_t)r0 * N + col)       = __nv_bfloat162{h00, h01};
                *(__nv_bfloat162*)(Cl + (size_t)r0 * N + col)       = __nv_bfloat162{l00, l01};
                *(__nv_bfloat162*)(Ch + (size_t)(r0 + 8) * N + col) = __nv_bfloat162{h10, h11};
                *(__nv_bfloat162*)(Cl + (size_t)(r0 + 8) * N + col) = __nv_bfloat162{l10, l11};
            }
        }
    }
}

// ====================================================================
// Window attention (unchanged from R1): one block per 64-token window
// ====================================================================
__global__ __launch_bounds__(256) void attn_kernel(
    const float* __restrict__ Q, const float* __restrict__ K,
    const float* __restrict__ V, float* __restrict__ O)
{
    __shared__ float sQ [64 * 32];
    __shared__ float sKV[64 * 33];
    __shared__ float sS [64 * 64];

    const int tid  = threadIdx.x;
    const size_t base = (size_t)blockIdx.x * 64 * E_DIM;

    const int kcol = tid & 63;
    const int q0   = (tid >> 6) * 16;
    float acc[16];
#pragma unroll
    for (int i = 0; i < 16; i++) acc[i] = 0.f;

    for (int c0 = 0; c0 < E_DIM; c0 += 32) {
        for (int idx = tid; idx < 64 * 32; idx += 256) {
            int r = idx >> 5, c = idx & 31;
            sQ [r * 32 + c] = Q[base + (size_t)r * E_DIM + c0 + c];
            sKV[r * 33 + c] = K[base + (size_t)r * E_DIM + c0 + c];
        }
        __syncthreads();
#pragma unroll
        for (int c = 0; c < 32; c++) {
            float kv = sKV[kcol * 33 + c];
#pragma unroll
            for (int i = 0; i < 16; i++)
                acc[i] += sQ[(q0 + i) * 32 + c] * kv;
        }
        __syncthreads();
    }
#pragma unroll
    for (int i = 0; i < 16; i++)
        sS[(q0 + i) * 64 + kcol] = acc[i] * SM_SCALE;
    __syncthreads();

    const int lane = tid & 31, wrp = tid >> 5;
    for (int r = wrp * 8; r < wrp * 8 + 8; r++) {
        float v0 = sS[r * 64 + lane];
        float v1 = sS[r * 64 + 32 + lane];
        float m = fmaxf(v0, v1);
#pragma unroll
        for (int o = 16; o > 0; o >>= 1)
            m = fmaxf(m, __shfl_xor_sync(0xffffffffu, m, o));
        float e0 = __expf(v0 - m), e1 = __expf(v1 - m);
        float s = e0 + e1;
#pragma unroll
        for (int o = 16; o > 0; o >>= 1)
            s += __shfl_xor_sync(0xffffffffu, s, o);
        float inv = 1.0f / s;
        sS[r * 64 + lane]      = e0 * inv;
        sS[r * 64 + 32 + lane] = e1 * inv;
    }
    __syncthreads();

    const int ecol = tid & 31;
    const int q0b  = (tid >> 5) * 8;
    for (int c0 = 0; c0 < E_DIM; c0 += 32) {
        for (int idx = tid; idx < 64 * 32; idx += 256) {
            int r = idx >> 5, c = idx & 31;
            sKV[r * 33 + c] = V[base + (size_t)r * E_DIM + c0 + c];
        }
        __syncthreads();
        float oacc[8];
#pragma unroll
        for (int i = 0; i < 8; i++) oacc[i] = 0.f;
#pragma unroll
        for (int k = 0; k < 64; k++) {
            float vv = sKV[k * 33 + ecol];
#pragma unroll
            for (int i = 0; i < 8; i++)
                oacc[i] += sS[(q0b + i) * 64 + k] * vv;
        }
#pragma unroll
        for (int i = 0; i < 8; i++)
            O[base + (size_t)(q0b + i) * E_DIM + c0 + ecol] = oacc[i];
        __syncthreads();
    }
}

// ====================================================================
// Y = LayerNorm(A + R) * g + b.  SPLIT: also emit hi/lo bf16 planes.
// ====================================================================
template <bool SPLIT>
__global__ __launch_bounds__(256) void add_ln_kernel(
    const float* __restrict__ A, const float* __restrict__ R,
    const float* __restrict__ g, const float* __restrict__ b,
    float* __restrict__ Y, __nv_bfloat16* __restrict__ Yh,
    __nv_bfloat16* __restrict__ Yl)
{
    const size_t off = (size_t)blockIdx.x * E_DIM;
    const int tid = threadIdx.x;
    float v[4];
    float s = 0.f, s2 = 0.f;
#pragma unroll
    for (int i = 0; i < 4; i++) {
        int c = tid + i * 256;
        float t = A[off + c] + R[off + c];
        v[i] = t; s += t; s2 += t * t;
    }
#pragma unroll
    for (int o = 16; o > 0; o >>= 1) {
        s  += __shfl_xor_sync(0xffffffffu, s,  o);
        s2 += __shfl_xor_sync(0xffffffffu, s2, o);
    }
    __shared__ float rs[8], rs2[8];
    __shared__ float s_mean, s_rstd;
    const int lane = tid & 31, wrp = tid >> 5;
    if (lane == 0) { rs[wrp] = s; rs2[wrp] = s2; }
    __syncthreads();
    if (tid == 0) {
        float a = 0.f, a2 = 0.f;
#pragma unroll
        for (int i = 0; i < 8; i++) { a += rs[i]; a2 += rs2[i]; }
        float mean = a * (1.0f / E_DIM);
        float var  = a2 * (1.0f / E_DIM) - mean * mean;
        s_mean = mean;
        s_rstd = rsqrtf(var + LN_EPS);
    }
    __syncthreads();
    const float mean = s_mean, rstd = s_rstd;
#pragma unroll
    for (int i = 0; i < 4; i++) {
        int c = tid + i * 256;
        float y = (v[i] - mean) * rstd * g[c] + b[c];
        if (Y) Y[off + c] = y;
        if (SPLIT) {
            __nv_bfloat16 hi, lo; split_f32(y, hi, lo);
            Yh[off + c] = hi; Yl[off + c] = lo;
        }
    }
}

// ====================================================================
extern "C" void kernel_launch(void* const* d_in, const int* in_sizes, int n_in,
                              void* d_out, int out_size)
{
    (void)in_sizes; (void)n_in; (void)out_size;
    const float* x   = (const float*)d_in[0];
    const float* Wq  = (const float*)d_in[1];
    const float* bq  = (const float*)d_in[2];
    const float* Wk  = (const float*)d_in[3];
    const float* bk  = (const float*)d_in[4];
    const float* Wv  = (const float*)d_in[5];
    const float* bv  = (const float*)d_in[6];
    const float* g1  = (const float*)d_in[7];
    const float* be1 = (const float*)d_in[8];
    const float* W1  = (const float*)d_in[9];
    const float* b1  = (const float*)d_in[10];
    const float* W2  = (const float*)d_in[11];
    const float* b2  = (const float*)d_in[12];
    const float* g2  = (const float*)d_in[13];
    const float* be2 = (const float*)d_in[14];
    float* out = (float*)d_out;

    float *q, *k, *v, *att, *x1, *f;
    cudaGetSymbolAddress((void**)&q,   g_q);
    cudaGetSymbolAddress((void**)&k,   g_k);
    cudaGetSymbolAddress((void**)&v,   g_v);
    cudaGetSymbolAddress((void**)&att, g_att);
    cudaGetSymbolAddress((void**)&x1,  g_x1);
    cudaGetSymbolAddress((void**)&f,   g_f);

    __nv_bfloat16 *xh, *xl, *x1h, *x1l, *hh, *hl;
    __nv_bfloat16 *wqh, *wql, *wkh, *wkl, *wvh, *wvl, *w1h, *w1l, *w2h, *w2l;
    cudaGetSymbolAddress((void**)&xh,  g_xh);
    cudaGetSymbolAddress((void**)&xl,  g_xl);
    cudaGetSymbolAddress((void**)&x1h, g_x1h);
    cudaGetSymbolAddress((void**)&x1l, g_x1l);
    cudaGetSymbolAddress((void**)&hh,  g_hh);
    cudaGetSymbolAddress((void**)&hl,  g_hl);
    cudaGetSymbolAddress((void**)&wqh, g_wqh);
    cudaGetSymbolAddress((void**)&wql, g_wql);
    cudaGetSymbolAddress((void**)&wkh, g_wkh);
    cudaGetSymbolAddress((void**)&wkl, g_wkl);
    cudaGetSymbolAddress((void**)&wvh, g_wvh);
    cudaGetSymbolAddress((void**)&wvl, g_wvl);
    cudaGetSymbolAddress((void**)&w1h, g_w1h);
    cudaGetSymbolAddress((void**)&w1l, g_w1l);
    cudaGetSymbolAddress((void**)&w2h, g_w2h);
    cudaGetSymbolAddress((void**)&w2l, g_w2l);

    cudaFuncSetAttribute(gemm_tn<0>, cudaFuncAttributeMaxDynamicSharedMemorySize, SMEM_TOTAL);
    cudaFuncSetAttribute(gemm_tn<1>, cudaFuncAttributeMaxDynamicSharedMemorySize, SMEM_TOTAL);

    dim3 blk(256);
    dim3 tblk(32, 8);

    // operand prep
    split_kernel<<<(M_TOT * E_DIM / 4 + 255) / 256, blk>>>(x, xh, xl, M_TOT * E_DIM / 4);
    wtrans_kernel<<<dim3(E_DIM / 32, E_DIM / 32), tblk>>>(Wq, wqh, wql, E_DIM, E_DIM);
    wtrans_kernel<<<dim3(E_DIM / 32, E_DIM / 32), tblk>>>(Wk, wkh, wkl, E_DIM, E_DIM);
    wtrans_kernel<<<dim3(E_DIM / 32, E_DIM / 32), tblk>>>(Wv, wvh, wvl, E_DIM, E_DIM);
    wtrans_kernel<<<dim3(HID_DIM / 32, E_DIM / 32), tblk>>>(W1, w1h, w1l, E_DIM, HID_DIM);
    wtrans_kernel<<<dim3(E_DIM / 32, HID_DIM / 32), tblk>>>(W2, w2h, w2l, HID_DIM, E_DIM);

    // QKV projections (tensor core)
    dim3 grid_qkv(E_DIM / BN, M_TOT / BM);
    gemm_tn<0><<<grid_qkv, blk, SMEM_TOTAL>>>(xh, xl, wqh, wql, bq, q, nullptr, nullptr, M_TOT, E_DIM, E_DIM);
    gemm_tn<0><<<grid_qkv, blk, SMEM_TOTAL>>>(xh, xl, wkh, wkl, bk, k, nullptr, nullptr, M_TOT, E_DIM, E_DIM);
    gemm_tn<0><<<grid_qkv, blk, SMEM_TOTAL>>>(xh, xl, wvh, wvl, bv, v, nullptr, nullptr, M_TOT, E_DIM, E_DIM);

    // per-window attention
    attn_kernel<<<NWIN, blk>>>(q, k, v, att);

    // x1 = LN(x + att), emit fp32 + bf16 planes
    add_ln_kernel<true><<<M_TOT, blk>>>(x, att, g1, be1, x1, x1h, x1l);

    // FFN1: h = relu(x1 @ W1 + b1), write hi/lo planes directly
    dim3 grid_f1(HID_DIM / BN, M_TOT / BM);
    gemm_tn<1><<<grid_f1, blk, SMEM_TOTAL>>>(x1h, x1l, w1h, w1l, b1, nullptr, hh, hl, M_TOT, HID_DIM, E_DIM);

    // FFN2: f = h @ W2 + b2 (fp32)
    dim3 grid_f2(E_DIM / BN, M_TOT / BM);
    gemm_tn<0><<<grid_f2, blk, SMEM_TOTAL>>>(hh, hl, w2h, w2l, b2, f, nullptr, nullptr, M_TOT, E_DIM, HID_DIM);

    // out = LN(x1 + f)
    add_ln_kernel<false><<<M_TOT, blk>>>(x1, f, g2, be2, out, nullptr, nullptr);
}

// round 3
// speedup vs baseline: 2.5370x; 1.0816x over previous
#include <cuda_runtime.h>
#include <cuda_bf16.h>
#include <math.h>
#include <stdint.h>

#define E_DIM   1024
#define HID_DIM 4096
#define M_TOT   16384          // B*S = 4*4096
#define NWIN    256            // 4*64 windows of 64 tokens
#define SM_SCALE 0.03125f      // 1024^-0.5
#define LN_EPS  1e-5f

#define BM 128
#define BN 128
#define BKE 32                 // K elems per stage
#define SROW 40                // padded row length in bf16 elems (80B)
#define PLANE_B 10240          // bytes per plane (128*40*2)
#define STAGE_B 40960          // 4 planes
#define SMEM_TOTAL (2*STAGE_B) // 81920

// -------- scratch (device globals; no allocation allowed) --------
__device__ float g_q  [M_TOT * E_DIM];
__device__ float g_k  [M_TOT * E_DIM];
__device__ float g_v  [M_TOT * E_DIM];
__device__ float g_att[M_TOT * E_DIM];
__device__ float g_x1 [M_TOT * E_DIM];
__device__ float g_f  [M_TOT * E_DIM];

__device__ __nv_bfloat16 g_xh [M_TOT * E_DIM];
__device__ __nv_bfloat16 g_xl [M_TOT * E_DIM];
__device__ __nv_bfloat16 g_x1h[M_TOT * E_DIM];
__device__ __nv_bfloat16 g_x1l[M_TOT * E_DIM];
__device__ __nv_bfloat16 g_hh [M_TOT * HID_DIM];
__device__ __nv_bfloat16 g_hl [M_TOT * HID_DIM];

__device__ __nv_bfloat16 g_wqh[E_DIM * E_DIM];
__device__ __nv_bfloat16 g_wql[E_DIM * E_DIM];
__device__ __nv_bfloat16 g_wkh[E_DIM * E_DIM];
__device__ __nv_bfloat16 g_wkl[E_DIM * E_DIM];
__device__ __nv_bfloat16 g_wvh[E_DIM * E_DIM];
__device__ __nv_bfloat16 g_wvl[E_DIM * E_DIM];
__device__ __nv_bfloat16 g_w1h[E_DIM * HID_DIM];
__device__ __nv_bfloat16 g_w1l[E_DIM * HID_DIM];
__device__ __nv_bfloat16 g_w2h[HID_DIM * E_DIM];
__device__ __nv_bfloat16 g_w2l[HID_DIM * E_DIM];

// ====================================================================
// helpers
// ====================================================================
__device__ __forceinline__ void split_f32(float x, __nv_bfloat16& hi, __nv_bfloat16& lo) {
    hi = __float2bfloat16(x);
    lo = __float2bfloat16(x - __bfloat162float(hi));
}

__device__ __forceinline__ void mma16816(float* c, const uint32_t* a, const uint32_t* b) {
    asm volatile(
        "mma.sync.aligned.m16n8k16.row.col.f32.bf16.bf16.f32 "
        "{%0,%1,%2,%3},{%4,%5,%6,%7},{%8,%9},{%0,%1,%2,%3};"
        : "+f"(c[0]), "+f"(c[1]), "+f"(c[2]), "+f"(c[3])
        : "r"(a[0]), "r"(a[1]), "r"(a[2]), "r"(a[3]), "r"(b[0]), "r"(b[1]));
}

__device__ __forceinline__ void ldsm4(uint32_t& r0, uint32_t& r1, uint32_t& r2, uint32_t& r3,
                                      uint32_t addr) {
    asm volatile("ldmatrix.sync.aligned.m8n8.x4.shared.b16 {%0,%1,%2,%3},[%4];"
                 : "=r"(r0), "=r"(r1), "=r"(r2), "=r"(r3) : "r"(addr));
}

// ====================================================================
// elementwise split: X fp32 -> hi/lo bf16 planes
// ====================================================================
__global__ __launch_bounds__(256) void split_kernel(
    const float* __restrict__ X, __nv_bfloat16* __restrict__ H,
    __nv_bfloat16* __restrict__ L, int n4)
{
    int i = blockIdx.x * 256 + threadIdx.x;
    if (i >= n4) return;
    float4 v = ((const float4*)X)[i];
    __nv_bfloat16 h[4], l[4];
    split_f32(v.x, h[0], l[0]); split_f32(v.y, h[1], l[1]);
    split_f32(v.z, h[2], l[2]); split_f32(v.w, h[3], l[3]);
    __nv_bfloat162* Hp = (__nv_bfloat162*)(H + (size_t)i * 4);
    __nv_bfloat162* Lp = (__nv_bfloat162*)(L + (size_t)i * 4);
    Hp[0] = __nv_bfloat162{h[0], h[1]}; Hp[1] = __nv_bfloat162{h[2], h[3]};
    Lp[0] = __nv_bfloat162{l[0], l[1]}; Lp[1] = __nv_bfloat162{l[2], l[3]};
}

// ====================================================================
// weight transpose + split: W[K,N] fp32 -> Th[N,K], Tl[N,K] bf16
// ====================================================================
__global__ __launch_bounds__(256) void wtrans_kernel(
    const float* __restrict__ W, __nv_bfloat16* __restrict__ Th,
    __nv_bfloat16* __restrict__ Tl, int K, int N)
{
    __shared__ float t[32][33];
    const int tx = threadIdx.x, ty = threadIdx.y;
    const int n0 = blockIdx.x * 32, k0 = blockIdx.y * 32;
#pragma unroll
    for (int i = ty; i < 32; i += 8)
        t[i][tx] = W[(size_t)(k0 + i) * N + n0 + tx];
    __syncthreads();
#pragma unroll
    for (int i = ty; i < 32; i += 8) {
        float v = t[tx][i];
        __nv_bfloat16 hi, lo; split_f32(v, hi, lo);
        size_t o = (size_t)(n0 + i) * K + k0 + tx;
        Th[o] = hi; Tl[o] = lo;
    }
}

// ====================================================================
// GEMM (TN): C[M,N] = (Ah+Al)[M,K] @ (Bh+Bl)[N,K]^T + bias
//   3-term bf16 split via mma.sync m16n8k16, ldmatrix fragment loads.
//   EPI=0: C fp32.  EPI=1: relu, write hi/lo bf16 planes Ch/Cl.
// ====================================================================
template <int EPI>
__global__ __launch_bounds__(256, 2) void gemm_tn(
    const __nv_bfloat16* __restrict__ Ah, const __nv_bfloat16* __restrict__ Al,
    const __nv_bfloat16* __restrict__ Bh, const __nv_bfloat16* __restrict__ Bl,
    const float* __restrict__ bias,
    float* __restrict__ C, __nv_bfloat16* __restrict__ Ch, __nv_bfloat16* __restrict__ Cl,
    int M, int N, int K)
{
    extern __shared__ __align__(16) char smem_raw[];
    const int tid = threadIdx.x;
    const int bm0 = blockIdx.y * BM;
    const int bn0 = blockIdx.x * BN;
    const int lane = tid & 31, w = tid >> 5;
    const int g = lane >> 2, q4 = lane & 3;
    const int wm = (w >> 2) * 64, wn = (w & 3) * 32;

    const uint32_t sbase = (uint32_t)__cvta_generic_to_shared(smem_raw);

    // ldmatrix per-lane base offsets (bytes within a plane, at k-chunk col 0)
    const uint32_t aoff = (uint32_t)((wm + (lane & 15)) * (SROW * 2) + (lane >> 4) * 16);
    const uint32_t boff = (uint32_t)((wn + (lane >> 4) * 8 + (lane & 7)) * (SROW * 2)
                                     + ((lane >> 3) & 1) * 16);

    float acc[4][4][4];
#pragma unroll
    for (int i = 0; i < 4; i++)
#pragma unroll
        for (int j = 0; j < 4; j++)
#pragma unroll
            for (int r = 0; r < 4; r++) acc[i][j][r] = 0.f;

    const __nv_bfloat16* gp[4] = {Ah, Al, Bh, Bl};
    const int rb[4] = {bm0, bm0, bn0, bn0};

    auto load_stage = [&](int s, int k0) {
        uint32_t b = sbase + s * STAGE_B;
#pragma unroll
        for (int p = 0; p < 4; p++) {
#pragma unroll
            for (int h2 = 0; h2 < 2; h2++) {
                int c = tid + h2 * 256;
                int row = c >> 2, cc = c & 3;
                uint32_t sa = b + p * PLANE_B + (row * SROW + cc * 8) * 2;
                const void* gptr = gp[p] + (size_t)(rb[p] + row) * K + k0 + cc * 8;
                asm volatile("cp.async.cg.shared.global [%0],[%1],16;\n" ::"r"(sa), "l"(gptr));
            }
        }
        asm volatile("cp.async.commit_group;\n");
    };

    load_stage(0, 0);
    asm volatile("cp.async.wait_group 0;\n");
    __syncthreads();

    for (int k0 = 0; k0 < K; k0 += BKE) {
        int s = (k0 >> 5) & 1;
        if (k0 + BKE < K) load_stage(s ^ 1, k0 + BKE);

        const uint32_t stg = sbase + s * STAGE_B;

#pragma unroll
        for (int ks = 0; ks < 2; ks++) {
            const uint32_t ka = stg + ks * 32 + aoff;                  // A-hi plane
            const uint32_t kb = stg + 2 * PLANE_B + ks * 32 + boff;    // B-hi plane

            uint32_t ah[4][4];
#pragma unroll
            for (int tm = 0; tm < 4; tm++)
                ldsm4(ah[tm][0], ah[tm][1], ah[tm][2], ah[tm][3], ka + tm * 16 * (SROW * 2));

            uint32_t bh[4][2];
            ldsm4(bh[0][0], bh[0][1], bh[1][0], bh[1][1], kb);
            ldsm4(bh[2][0], bh[2][1], bh[3][0], bh[3][1], kb + 16 * (SROW * 2));

#pragma unroll
            for (int tm = 0; tm < 4; tm++)
#pragma unroll
                for (int tn = 0; tn < 4; tn++)
                    mma16816(acc[tm][tn], ah[tm], bh[tn]);

            uint32_t al[4][4];
#pragma unroll
            for (int tm = 0; tm < 4; tm++)
                ldsm4(al[tm][0], al[tm][1], al[tm][2], al[tm][3],
                      ka + PLANE_B + tm * 16 * (SROW * 2));

#pragma unroll
            for (int tm = 0; tm < 4; tm++)
#pragma unroll
                for (int tn = 0; tn < 4; tn++)
                    mma16816(acc[tm][tn], al[tm], bh[tn]);

            uint32_t bl[4][2];
            ldsm4(bl[0][0], bl[0][1], bl[1][0], bl[1][1], kb + PLANE_B);
            ldsm4(bl[2][0], bl[2][1], bl[3][0], bl[3][1], kb + PLANE_B + 16 * (SROW * 2));

#pragma unroll
            for (int tm = 0; tm < 4; tm++)
#pragma unroll
                for (int tn = 0; tn < 4; tn++)
                    mma16816(acc[tm][tn], ah[tm], bl[tn]);
        }
        if (k0 + BKE < K) asm volatile("cp.async.wait_group 0;\n");
        __syncthreads();
    }

    // epilogue
#pragma unroll
    for (int tm = 0; tm < 4; tm++) {
#pragma unroll
        for (int tn = 0; tn < 4; tn++) {
            int r0 = bm0 + wm + tm * 16 + g;
            int col = bn0 + wn + tn * 8 + q4 * 2;
            float b0 = bias[col], b1 = bias[col + 1];
            float v00 = acc[tm][tn][0] + b0, v01 = acc[tm][tn][1] + b1;
            float v10 = acc[tm][tn][2] + b0, v11 = acc[tm][tn][3] + b1;
            if (EPI == 0) {
                *(float2*)(C + (size_t)r0 * N + col) = make_float2(v00, v01);
                *(float2*)(C + (size_t)(r0 + 8) * N + col) = make_float2(v10, v11);
            } else {
                v00 = fmaxf(v00, 0.f); v01 = fmaxf(v01, 0.f);
                v10 = fmaxf(v10, 0.f); v11 = fmaxf(v11, 0.f);
                __nv_bfloat16 h00, l00, h01, l01, h10, l10, h11, l11;
                split_f32(v00, h00, l00); split_f32(v01, h01, l01);
                split_f32(v10, h10, l10); split_f32(v11, h11, l11);
                *(__nv_bfloat162*)(Ch + (size_t)r0 * N + col)       = __nv_bfloat162{h00, h01};
                *(__nv_bfloat162*)(Cl + (size_t)r0 * N + col)       = __nv_bfloat162{l00, l01};
                *(__nv_bfloat162*)(Ch + (size_t)(r0 + 8) * N + col) = __nv_bfloat162{h10, h11};
                *(__nv_bfloat162*)(Cl + (size_t)(r0 + 8) * N + col) = __nv_bfloat162{l10, l11};
            }
        }
    }
}

// ====================================================================
// Window attention: one block per 64-token window
// ====================================================================
__global__ __launch_bounds__(256) void attn_kernel(
    const float* __restrict__ Q, const float* __restrict__ K,
    const float* __restrict__ V, float* __restrict__ O)
{
    __shared__ float sQ [64 * 32];
    __shared__ float sKV[64 * 33];
    __shared__ float sS [64 * 64];

    const int tid  = threadIdx.x;
    const size_t base = (size_t)blockIdx.x * 64 * E_DIM;

    const int kcol = tid & 63;
    const int q0   = (tid >> 6) * 16;
    float acc[16];
#pragma unroll
    for (int i = 0; i < 16; i++) acc[i] = 0.f;

    for (int c0 = 0; c0 < E_DIM; c0 += 32) {
        for (int idx = tid; idx < 64 * 32; idx += 256) {
            int r = idx >> 5, c = idx & 31;
            sQ [r * 32 + c] = Q[base + (size_t)r * E_DIM + c0 + c];
            sKV[r * 33 + c] = K[base + (size_t)r * E_DIM + c0 + c];
        }
        __syncthreads();
#pragma unroll
        for (int c = 0; c < 32; c++) {
            float kv = sKV[kcol * 33 + c];
#pragma unroll
            for (int i = 0; i < 16; i++)
                acc[i] += sQ[(q0 + i) * 32 + c] * kv;
        }
        __syncthreads();
    }
#pragma unroll
    for (int i = 0; i < 16; i++)
        sS[(q0 + i) * 64 + kcol] = acc[i] * SM_SCALE;
    __syncthreads();

    const int lane = tid & 31, wrp = tid >> 5;
    for (int r = wrp * 8; r < wrp * 8 + 8; r++) {
        float v0 = sS[r * 64 + lane];
        float v1 = sS[r * 64 + 32 + lane];
        float m = fmaxf(v0, v1);
#pragma unroll
        for (int o = 16; o > 0; o >>= 1)
            m = fmaxf(m, __shfl_xor_sync(0xffffffffu, m, o));
        float e0 = __expf(v0 - m), e1 = __expf(v1 - m);
        float s = e0 + e1;
#pragma unroll
        for (int o = 16; o > 0; o >>= 1)
            s += __shfl_xor_sync(0xffffffffu, s, o);
        float inv = 1.0f / s;
        sS[r * 64 + lane]      = e0 * inv;
        sS[r * 64 + 32 + lane] = e1 * inv;
    }
    __syncthreads();

    const int ecol = tid & 31;
    const int q0b  = (tid >> 5) * 8;
    for (int c0 = 0; c0 < E_DIM; c0 += 32) {
        for (int idx = tid; idx < 64 * 32; idx += 256) {
            int r = idx >> 5, c = idx & 31;
            sKV[r * 33 + c] = V[base + (size_t)r * E_DIM + c0 + c];
        }
        __syncthreads();
        float oacc[8];
#pragma unroll
        for (int i = 0; i < 8; i++) oacc[i] = 0.f;
#pragma unroll
        for (int k = 0; k < 64; k++) {
            float vv = sKV[k * 33 + ecol];
#pragma unroll
            for (int i = 0; i < 8; i++)
                oacc[i] += sS[(q0b + i) * 64 + k] * vv;
        }
#pragma unroll
        for (int i = 0; i < 8; i++)
            O[base + (size_t)(q0b + i) * E_DIM + c0 + ecol] = oacc[i];
        __syncthreads();
    }
}

// ====================================================================
// Y = LayerNorm(A + R) * g + b.  SPLIT: also emit hi/lo bf16 planes.
// ====================================================================
template <bool SPLIT>
__global__ __launch_bounds__(256) void add_ln_kernel(
    const float* __restrict__ A, const float* __restrict__ R,
    const float* __restrict__ g, const float* __restrict__ b,
    float* __restrict__ Y, __nv_bfloat16* __restrict__ Yh,
    __nv_bfloat16* __restrict__ Yl)
{
    const size_t off = (size_t)blockIdx.x * E_DIM;
    const int tid = threadIdx.x;
    float v[4];
    float s = 0.f, s2 = 0.f;
#pragma unroll
    for (int i = 0; i < 4; i++) {
        int c = tid + i * 256;
        float t = A[off + c] + R[off + c];
        v[i] = t; s += t; s2 += t * t;
    }
#pragma unroll
    for (int o = 16; o > 0; o >>= 1) {
        s  += __shfl_xor_sync(0xffffffffu, s,  o);
        s2 += __shfl_xor_sync(0xffffffffu, s2, o);
    }
    __shared__ float rs[8], rs2[8];
    __shared__ float s_mean, s_rstd;
    const int lane = tid & 31, wrp = tid >> 5;
    if (lane == 0) { rs[wrp] = s; rs2[wrp] = s2; }
    __syncthreads();
    if (tid == 0) {
        float a = 0.f, a2 = 0.f;
#pragma unroll
        for (int i = 0; i < 8; i++) { a += rs[i]; a2 += rs2[i]; }
        float mean = a * (1.0f / E_DIM);
        float var  = a2 * (1.0f / E_DIM) - mean * mean;
        s_mean = mean;
        s_rstd = rsqrtf(var + LN_EPS);
    }
    __syncthreads();
    const float mean = s_mean, rstd = s_rstd;
#pragma unroll
    for (int i = 0; i < 4; i++) {
        int c = tid + i * 256;
        float y = (v[i] - mean) * rstd * g[c] + b[c];
        if (Y) Y[off + c] = y;
        if (SPLIT) {
            __nv_bfloat16 hi, lo; split_f32(y, hi, lo);
            Yh[off + c] = hi; Yl[off + c] = lo;
        }
    }
}

// ====================================================================
extern "C" void kernel_launch(void* const* d_in, const int* in_sizes, int n_in,
                              void* d_out, int out_size)
{
    (void)in_sizes; (void)n_in; (void)out_size;
    const float* x   = (const float*)d_in[0];
    const float* Wq  = (const float*)d_in[1];
    const float* bq  = (const float*)d_in[2];
    const float* Wk  = (const float*)d_in[3];
    const float* bk  = (const float*)d_in[4];
    const float* Wv  = (const float*)d_in[5];
    const float* bv  = (const float*)d_in[6];
    const float* g1  = (const float*)d_in[7];
    const float* be1 = (const float*)d_in[8];
    const float* W1  = (const float*)d_in[9];
    const float* b1  = (const float*)d_in[10];
    const float* W2  = (const float*)d_in[11];
    const float* b2  = (const float*)d_in[12];
    const float* g2  = (const float*)d_in[13];
    const float* be2 = (const float*)d_in[14];
    float* out = (float*)d_out;

    float *q, *k, *v, *att, *x1, *f;
    cudaGetSymbolAddress((void**)&q,   g_q);
    cudaGetSymbolAddress((void**)&k,   g_k);
    cudaGetSymbolAddress((void**)&v,   g_v);
    cudaGetSymbolAddress((void**)&att, g_att);
    cudaGetSymbolAddress((void**)&x1,  g_x1);
    cudaGetSymbolAddress((void**)&f,   g_f);

    __nv_bfloat16 *xh, *xl, *x1h, *x1l, *hh, *hl;
    __nv_bfloat16 *wqh, *wql, *wkh, *wkl, *wvh, *wvl, *w1h, *w1l, *w2h, *w2l;
    cudaGetSymbolAddress((void**)&xh,  g_xh);
    cudaGetSymbolAddress((void**)&xl,  g_xl);
    cudaGetSymbolAddress((void**)&x1h, g_x1h);
    cudaGetSymbolAddress((void**)&x1l, g_x1l);
    cudaGetSymbolAddress((void**)&hh,  g_hh);
    cudaGetSymbolAddress((void**)&hl,  g_hl);
    cudaGetSymbolAddress((void**)&wqh, g_wqh);
    cudaGetSymbolAddress((void**)&wql, g_wql);
    cudaGetSymbolAddress((void**)&wkh, g_wkh);
    cudaGetSymbolAddress((void**)&wkl, g_wkl);
    cudaGetSymbolAddress((void**)&wvh, g_wvh);
    cudaGetSymbolAddress((void**)&wvl, g_wvl);
    cudaGetSymbolAddress((void**)&w1h, g_w1h);
    cudaGetSymbolAddress((void**)&w1l, g_w1l);
    cudaGetSymbolAddress((void**)&w2h, g_w2h);
    cudaGetSymbolAddress((void**)&w2l, g_w2l);

    cudaFuncSetAttribute(gemm_tn<0>, cudaFuncAttributeMaxDynamicSharedMemorySize, SMEM_TOTAL);
    cudaFuncSetAttribute(gemm_tn<1>, cudaFuncAttributeMaxDynamicSharedMemorySize, SMEM_TOTAL);

    dim3 blk(256);
    dim3 tblk(32, 8);

    // operand prep
    split_kernel<<<(M_TOT * E_DIM / 4 + 255) / 256, blk>>>(x, xh, xl, M_TOT * E_DIM / 4);
    wtrans_kernel<<<dim3(E_DIM / 32, E_DIM / 32), tblk>>>(Wq, wqh, wql, E_DIM, E_DIM);
    wtrans_kernel<<<dim3(E_DIM / 32, E_DIM / 32), tblk>>>(Wk, wkh, wkl, E_DIM, E_DIM);
    wtrans_kernel<<<dim3(E_DIM / 32, E_DIM / 32), tblk>>>(Wv, wvh, wvl, E_DIM, E_DIM);
    wtrans_kernel<<<dim3(HID_DIM / 32, E_DIM / 32), tblk>>>(W1, w1h, w1l, E_DIM, HID_DIM);
    wtrans_kernel<<<dim3(E_DIM / 32, HID_DIM / 32), tblk>>>(W2, w2h, w2l, HID_DIM, E_DIM);

    // QKV projections (tensor core)
    dim3 grid_qkv(E_DIM / BN, M_TOT / BM);
    gemm_tn<0><<<grid_qkv, blk, SMEM_TOTAL>>>(xh, xl, wqh, wql, bq, q, nullptr, nullptr, M_TOT, E_DIM, E_DIM);
    gemm_tn<0><<<grid_qkv, blk, SMEM_TOTAL>>>(xh, xl, wkh, wkl, bk, k, nullptr, nullptr, M_TOT, E_DIM, E_DIM);
    gemm_tn<0><<<grid_qkv, blk, SMEM_TOTAL>>>(xh, xl, wvh, wvl, bv, v, nullptr, nullptr, M_TOT, E_DIM, E_DIM);

    // per-window attention
    attn_kernel<<<NWIN, blk>>>(q, k, v, att);

    // x1 = LN(x + att), emit fp32 + bf16 planes
    add_ln_kernel<true><<<M_TOT, blk>>>(x, att, g1, be1, x1, x1h, x1l);

    // FFN1: h = relu(x1 @ W1 + b1), write hi/lo planes directly
    dim3 grid_f1(HID_DIM / BN, M_TOT / BM);
    gemm_tn<1><<<grid_f1, blk, SMEM_TOTAL>>>(x1h, x1l, w1h, w1l, b1, nullptr, hh, hl, M_TOT, HID_DIM, E_DIM);

    // FFN2: f = h @ W2 + b2 (fp32)
    dim3 grid_f2(E_DIM / BN, M_TOT / BM);
    gemm_tn<0><<<grid_f2, blk, SMEM_TOTAL>>>(hh, hl, w2h, w2l, b2, f, nullptr, nullptr, M_TOT, E_DIM, HID_DIM);

    // out = LN(x1 + f)
    add_ln_kernel<false><<<M_TOT, blk>>>(x1, f, g2, be2, out, nullptr, nullptr);
}